// round 1
// baseline (speedup 1.0000x reference)
#include <cuda_runtime.h>
#include <cuda_fp16.h>
#include <cstdint>

// Problem constants
#define BB    64
#define HH    64
#define WWID  64
#define CINC  128
#define COUTC 256
#define KHW   3
#define HOUT  62
#define WOUT  62
#define MM    3844   // 62*62
#define KKTOT 1152   // 9*128
#define NNTOT 256

// GEMM tiling
#define BM 128
#define BN 128
#define BK 32
#define NIT (KKTOT / BK)   // 36

// Scratch: fp16 copies of X and per-sample noisy weights (allocation-free rule:
// __device__ globals are the sanctioned scratch mechanism).
__device__ __half g_Xh[(size_t)BB * HH * WWID * CINC];        // 67 MB
__device__ __half g_Wh[(size_t)BB * KKTOT * COUTC];           // 38 MB

// ---------------------------------------------------------------------------
// Prep kernel 1: X f32 -> fp16
// ---------------------------------------------------------------------------
__global__ void convert_x_kernel(const float* __restrict__ X) {
    size_t i = ((size_t)blockIdx.x * blockDim.x + threadIdx.x) * 4;
    float4 v = *reinterpret_cast<const float4*>(X + i);
    __half2 h0 = __floats2half2_rn(v.x, v.y);
    __half2 h1 = __floats2half2_rn(v.z, v.w);
    uint2 o;
    o.x = *reinterpret_cast<uint32_t*>(&h0);
    o.y = *reinterpret_cast<uint32_t*>(&h1);
    *reinterpret_cast<uint2*>(g_Xh + i) = o;
}

// ---------------------------------------------------------------------------
// Prep kernel 2: memW[b,k,co] = W[k,co] * Werr[b,k,co]  -> fp16
// k = (kh*3+kw)*128 + ci ; co contiguous. Werr is already in this layout.
// ---------------------------------------------------------------------------
__global__ void convert_w_kernel(const float* __restrict__ W,
                                 const float* __restrict__ Werr) {
    size_t i = ((size_t)blockIdx.x * blockDim.x + threadIdx.x) * 4;
    size_t wi = i % ((size_t)KKTOT * COUTC);
    float4 w = *reinterpret_cast<const float4*>(W + wi);
    float4 e = *reinterpret_cast<const float4*>(Werr + i);
    __half2 h0 = __floats2half2_rn(w.x * e.x, w.y * e.y);
    __half2 h1 = __floats2half2_rn(w.z * e.z, w.w * e.w);
    uint2 o;
    o.x = *reinterpret_cast<uint32_t*>(&h0);
    o.y = *reinterpret_cast<uint32_t*>(&h1);
    *reinterpret_cast<uint2*>(g_Wh + i) = o;
}

// ---------------------------------------------------------------------------
// Inline PTX helpers
// ---------------------------------------------------------------------------
__device__ __forceinline__ void cp16(uint32_t dst, const void* src) {
    asm volatile("cp.async.cg.shared.global [%0], [%1], 16;\n" :: "r"(dst), "l"(src));
}
__device__ __forceinline__ void cp_commit() {
    asm volatile("cp.async.commit_group;\n" ::: "memory");
}
__device__ __forceinline__ void cp_wait0() {
    asm volatile("cp.async.wait_group 0;\n" ::: "memory");
}
__device__ __forceinline__ void ldmatrix_x4(uint32_t* r, uint32_t addr) {
    asm volatile("ldmatrix.sync.aligned.m8n8.x4.shared.b16 {%0,%1,%2,%3}, [%4];\n"
                 : "=r"(r[0]), "=r"(r[1]), "=r"(r[2]), "=r"(r[3]) : "r"(addr));
}
__device__ __forceinline__ void ldmatrix_x2_trans(uint32_t* r, uint32_t addr) {
    asm volatile("ldmatrix.sync.aligned.m8n8.x2.trans.shared.b16 {%0,%1}, [%2];\n"
                 : "=r"(r[0]), "=r"(r[1]) : "r"(addr));
}
__device__ __forceinline__ void mma16816(float* c, const uint32_t* a, const uint32_t* b) {
    asm volatile(
        "mma.sync.aligned.m16n8k16.row.col.f32.f16.f16.f32 "
        "{%0,%1,%2,%3}, {%4,%5,%6,%7}, {%8,%9}, {%0,%1,%2,%3};\n"
        : "+f"(c[0]), "+f"(c[1]), "+f"(c[2]), "+f"(c[3])
        : "r"(a[0]), "r"(a[1]), "r"(a[2]), "r"(a[3]), "r"(b[0]), "r"(b[1]));
}

// ---------------------------------------------------------------------------
// Main kernel: per-sample implicit-GEMM conv.
// grid = (N/BN=2, ceil(M/BM)=31, B=64), block = 256 (8 warps: 2 along M x 4 along N)
// Warp tile 64x32; per warp 4x4 mma fragments of 16x8, k16 steps.
// ---------------------------------------------------------------------------
__global__ __launch_bounds__(256)
void conv_gemm_kernel(const float* __restrict__ bias,
                      const float* __restrict__ Berr,
                      float* __restrict__ out) {
    const int b  = blockIdx.z;
    const int m0 = blockIdx.y * BM;
    const int n0 = blockIdx.x * BN;

    __shared__ __align__(16) __half As[2][BM][BK + 8];   // row stride 80B (conflict-free)
    __shared__ __align__(16) __half Bs[2][BK][BN + 8];   // row stride 272B (conflict-free)

    const int tid  = threadIdx.x;
    const int warp = tid >> 5;
    const int lane = tid & 31;
    const int wm = warp >> 2;   // 0..1  (M)
    const int wn = warp & 3;    // 0..3  (N)

    float acc[4][4][4];
    #pragma unroll
    for (int mf = 0; mf < 4; mf++)
        #pragma unroll
        for (int nf = 0; nf < 4; nf++)
            #pragma unroll
            for (int r = 0; r < 4; r++) acc[mf][nf][r] = 0.f;

    // Precompute A-load descriptors: 512 16B chunks per stage -> 2 per thread.
    int arow[2], aseg[2];
    size_t abase[2];
    #pragma unroll
    for (int j = 0; j < 2; j++) {
        int c = tid + j * 256;
        arow[j] = c >> 2;
        aseg[j] = c & 3;
        int m = m0 + arow[j];
        if (m >= MM) m = 0;                       // clamp: load valid data, discard at store
        int ho = m / WOUT;
        int wo = m - ho * WOUT;
        abase[j] = (((size_t)b * HH + ho) * WWID + wo) * CINC;
    }
    // B-load descriptors: 512 16B chunks -> 2 per thread.
    int brow[2], bseg[2];
    #pragma unroll
    for (int j = 0; j < 2; j++) {
        int c = tid + j * 256;
        brow[j] = c >> 4;
        bseg[j] = c & 15;
    }

    auto issue_tiles = [&](int it, int s) {
        const int k0 = it * BK;
        const int kk = k0 >> 7;          // kernel tap 0..8 (BK=32 divides CIN=128)
        const int c0 = k0 & 127;
        const int kh = kk / 3;
        const int kw = kk - kh * 3;
        #pragma unroll
        for (int j = 0; j < 2; j++) {
            const __half* src = g_Xh + abase[j] + ((size_t)kh * WWID + kw) * CINC
                                + c0 + aseg[j] * 8;
            uint32_t dst = (uint32_t)__cvta_generic_to_shared(&As[s][arow[j]][aseg[j] * 8]);
            cp16(dst, src);
        }
        #pragma unroll
        for (int j = 0; j < 2; j++) {
            const __half* src = g_Wh + (((size_t)b * KKTOT) + k0 + brow[j]) * COUTC
                                + n0 + bseg[j] * 8;
            uint32_t dst = (uint32_t)__cvta_generic_to_shared(&Bs[s][brow[j]][bseg[j] * 8]);
            cp16(dst, src);
        }
    };

    issue_tiles(0, 0);
    cp_commit();

    for (int it = 0; it < NIT; it++) {
        const int s = it & 1;
        cp_wait0();
        __syncthreads();
        if (it + 1 < NIT) { issue_tiles(it + 1, s ^ 1); cp_commit(); }

        #pragma unroll
        for (int ks = 0; ks < 2; ks++) {
            uint32_t afr[4][4];
            const int arL  = wm * 64 + (lane & 15);
            const int acol = ks * 16 + ((lane >> 4) << 3);
            #pragma unroll
            for (int mf = 0; mf < 4; mf++) {
                uint32_t addr = (uint32_t)__cvta_generic_to_shared(&As[s][arL + mf * 16][acol]);
                ldmatrix_x4(afr[mf], addr);
            }
            uint32_t bfr[4][2];
            const int brL = ks * 16 + (lane & 15);
            #pragma unroll
            for (int nf = 0; nf < 4; nf++) {
                uint32_t addr = (uint32_t)__cvta_generic_to_shared(&Bs[s][brL][wn * 32 + nf * 8]);
                ldmatrix_x2_trans(bfr[nf], addr);
            }
            #pragma unroll
            for (int mf = 0; mf < 4; mf++)
                #pragma unroll
                for (int nf = 0; nf < 4; nf++)
                    mma16816(acc[mf][nf], afr[mf], bfr[nf]);
        }
        // top-of-loop __syncthreads covers the write-after-read hazard for stage s
    }

    // Epilogue: add per-sample noisy bias, write f32.
    const int gid = lane >> 2;   // 0..7 (row within 16x8 frag)
    const int tg  = lane & 3;    // col pair
    #pragma unroll
    for (int nf = 0; nf < 4; nf++) {
        const int cc = n0 + wn * 32 + nf * 8 + tg * 2;
        const float mb0 = bias[cc]     * Berr[b * COUTC + cc];
        const float mb1 = bias[cc + 1] * Berr[b * COUTC + cc + 1];
        #pragma unroll
        for (int mf = 0; mf < 4; mf++) {
            const int r0 = m0 + wm * 64 + mf * 16 + gid;
            if (r0 < MM) {
                float2 v = make_float2(acc[mf][nf][0] + mb0, acc[mf][nf][1] + mb1);
                *reinterpret_cast<float2*>(&out[((size_t)b * MM + r0) * NNTOT + cc]) = v;
            }
            const int r1 = r0 + 8;
            if (r1 < MM) {
                float2 v = make_float2(acc[mf][nf][2] + mb0, acc[mf][nf][3] + mb1);
                *reinterpret_cast<float2*>(&out[((size_t)b * MM + r1) * NNTOT + cc]) = v;
            }
        }
    }
}

// ---------------------------------------------------------------------------
// Launch
// ---------------------------------------------------------------------------
extern "C" void kernel_launch(void* const* d_in, const int* in_sizes, int n_in,
                              void* d_out, int out_size) {
    (void)in_sizes; (void)n_in; (void)out_size;
    const float* X    = (const float*)d_in[0];
    const float* W    = (const float*)d_in[1];
    const float* bias = (const float*)d_in[2];
    const float* Werr = (const float*)d_in[3];
    const float* Berr = (const float*)d_in[4];
    float* out = (float*)d_out;

    // X: 64*64*64*128 = 33,554,432 elems / 4 per thread / 256 = 32768 blocks
    convert_x_kernel<<<32768, 256>>>(X);
    // Werr: 64*1152*256 = 18,874,368 / 4 / 256 = 18432 blocks
    convert_w_kernel<<<18432, 256>>>(W, Werr);

    dim3 grid(NNTOT / BN, (MM + BM - 1) / BM, BB);   // (2, 31, 64)
    conv_gemm_kernel<<<grid, 256>>>(bias, Berr, out);
}